// round 16
// baseline (speedup 1.0000x reference)
#include <cuda_runtime.h>
#include <cuda_bf16.h>
#include <cuda_fp16.h>
#include <cstdint>

#define NUU 200000
#define NII 100000
#define NT  (NUU + NII)
#define NBLK ((NT + 1023) / 1024)   // 293

// ---------------- scratch (static device globals; no allocation) ----------------
// agg: per node 128 fp16 (256B), LINEAR layout. GEMM converts to bf16 hi/lo in smem.
__device__ __half g_aggf[(size_t)NT * 128];
__device__ int g_cnt[NT];
__device__ int g_off[NT + 1];
__device__ int g_cur[NT];
__device__ volatile long long g_blkDesc[512];   // (value<<2)|state ; 0=inv,1=agg,2=prefix
__device__ int g_nbr[1200000 + 64];
// combined weights, transposed to [N=128][K=256], bf16 hi/lo
__device__ __nv_bfloat16 g_WuT_hi[128 * 256];
__device__ __nv_bfloat16 g_WuT_lo[128 * 256];
__device__ __nv_bfloat16 g_WiT_hi[128 * 256];
__device__ __nv_bfloat16 g_WiT_lo[128 * 256];
__device__ float g_cu[128];
__device__ float g_ci[128];

__device__ __forceinline__ uint32_t smem_u32(const void* p) {
    uint32_t a;
    asm("{ .reg .u64 t; cvta.to.shared.u64 t, %1; cvt.u32.u64 %0, t; }" : "=r"(a) : "l"(p));
    return a;
}
__device__ __forceinline__ void cpa16(uint32_t d, const void* s) {
    asm volatile("cp.async.cg.shared.global [%0], [%1], 16;" :: "r"(d), "l"(s));
}
#define CP_COMMIT() asm volatile("cp.async.commit_group;" ::: "memory")
#define CP_WAIT0()  asm volatile("cp.async.wait_group 0;" ::: "memory")

// ---------------- CSR build ----------------
__global__ void hist_all(const int* __restrict__ diu, int neiu,
                         const int* __restrict__ dui, int neui) {
    int i = blockIdx.x * blockDim.x + threadIdx.x;
    if (i < neiu) atomicAdd(&g_cnt[diu[i]], 1);
    else if (i < neiu + neui) atomicAdd(&g_cnt[NUU + dui[i - neiu]], 1);
}

// one-pass decoupled-lookback exclusive scan of g_cnt -> g_off/g_cur
__global__ void scan_chained(int totE) {
    __shared__ int sh[1024];
    __shared__ int s_pref;
    int t = threadIdx.x;
    int b = blockIdx.x;
    int idx = b * 1024 + t;
    int c = (idx < NT) ? g_cnt[idx] : 0;
    sh[t] = c;
    __syncthreads();
#pragma unroll
    for (int o = 1; o < 1024; o <<= 1) {
        int v = (t >= o) ? sh[t - o] : 0;
        __syncthreads();
        sh[t] += v;
        __syncthreads();
    }
    int total = sh[1023];

    if (b == 0) {
        if (t == 0) {
            s_pref = 0;
            g_blkDesc[0] = ((long long)total << 2) | 2;
        }
        __syncthreads();
    } else {
        if (t == 0)
            g_blkDesc[b] = ((long long)total << 2) | 1;
        if (t < 32) {
            int lane = t;
            int run = 0;
            int look = b - 1;
            while (true) {
                int ix = look - lane;
                int st, val;
                if (ix >= 0) {
                    long long d;
                    do { d = g_blkDesc[ix]; } while ((d & 3) == 0);
                    st = (int)(d & 3);
                    val = (int)(d >> 2);
                } else { st = 2; val = 0; }
                unsigned mask = __ballot_sync(0xffffffffu, st == 2);
                int firstLane = mask ? (__ffs(mask) - 1) : 32;
                int contrib = (lane <= firstLane) ? val : 0;
#pragma unroll
                for (int o = 16; o > 0; o >>= 1)
                    contrib += __shfl_xor_sync(0xffffffffu, contrib, o);
                run += contrib;
                if (mask) break;
                look -= 32;
            }
            if (lane == 0) {
                s_pref = run;
                g_blkDesc[b] = ((long long)(run + total) << 2) | 2;
            }
        }
        __syncthreads();
    }

    if (idx < NT) {
        int v = s_pref + sh[t] - c;
        g_off[idx] = v;
        g_cur[idx] = v;
    }
    if (idx == 0) g_off[NT] = totE;
}

__global__ void fill_all(const int* __restrict__ siu, const int* __restrict__ diu, int neiu,
                         const int* __restrict__ sui, const int* __restrict__ dui, int neui) {
    int i = blockIdx.x * blockDim.x + threadIdx.x;
    if (i < neiu) {
        int p = atomicAdd(&g_cur[diu[i]], 1);
        g_nbr[p] = siu[i];
    } else if (i < neiu + neui) {
        int j = i - neiu;
        int p = atomicAdd(&g_cur[NUU + dui[j]], 1);
        g_nbr[p] = sui[j];
    }
}

__device__ __forceinline__ uint32_t packbf2(float a, float b) {
    __nv_bfloat162 p;
    p.x = __float2bfloat16_rn(a);
    p.y = __float2bfloat16_rn(b);
    return *reinterpret_cast<uint32_t*>(&p);
}
__device__ __forceinline__ uint32_t packh2(float a, float b) {
    __half2 p;
    p.x = __float2half_rn(a);
    p.y = __float2half_rn(b);
    return *reinterpret_cast<uint32_t*>(&p);
}

// ---------------- gather: one warp per dst node; mean -> fp16, linear ----------------
__global__ void gather_part(const float* __restrict__ xs, int nodeBeg, int nodeEnd) {
    int w = nodeBeg + ((blockIdx.x * blockDim.x + threadIdx.x) >> 5);
    int lane = threadIdx.x & 31;
    if (w >= nodeEnd) return;
    int o = g_off[w], e = g_off[w + 1];
    float a0 = 0.f, a1 = 0.f, a2 = 0.f, a3 = 0.f;
    int kk = lane * 4;
    int p = o;
    for (; p + 3 < e; p += 4) {
        int s0 = __ldg(&g_nbr[p]);
        int s1 = __ldg(&g_nbr[p + 1]);
        int s2 = __ldg(&g_nbr[p + 2]);
        int s3 = __ldg(&g_nbr[p + 3]);
        float4 v0 = *reinterpret_cast<const float4*>(xs + (size_t)s0 * 128 + kk);
        float4 v1 = *reinterpret_cast<const float4*>(xs + (size_t)s1 * 128 + kk);
        float4 v2 = *reinterpret_cast<const float4*>(xs + (size_t)s2 * 128 + kk);
        float4 v3 = *reinterpret_cast<const float4*>(xs + (size_t)s3 * 128 + kk);
        a0 += (v0.x + v1.x) + (v2.x + v3.x);
        a1 += (v0.y + v1.y) + (v2.y + v3.y);
        a2 += (v0.z + v1.z) + (v2.z + v3.z);
        a3 += (v0.w + v1.w) + (v2.w + v3.w);
    }
    if (p + 1 < e) {
        int s0 = __ldg(&g_nbr[p]);
        int s1 = __ldg(&g_nbr[p + 1]);
        float4 v0 = *reinterpret_cast<const float4*>(xs + (size_t)s0 * 128 + kk);
        float4 v1 = *reinterpret_cast<const float4*>(xs + (size_t)s1 * 128 + kk);
        a0 += v0.x + v1.x; a1 += v0.y + v1.y; a2 += v0.z + v1.z; a3 += v0.w + v1.w;
        p += 2;
    }
    if (p < e) {
        int s0 = __ldg(&g_nbr[p]);
        float4 v0 = *reinterpret_cast<const float4*>(xs + (size_t)s0 * 128 + kk);
        a0 += v0.x; a1 += v0.y; a2 += v0.z; a3 += v0.w;
    }
    float inv = 1.0f / (float)max(e - o, 1);
    a0 *= inv; a1 *= inv; a2 *= inv; a3 *= inv;
    uint2 hv = make_uint2(packh2(a0, a1), packh2(a2, a3));
    *reinterpret_cast<uint2*>(g_aggf + (size_t)w * 128 + kk) = hv;
}

// ---------------- combine weights ----------------
__global__ void combine_w(const float* __restrict__ WlIU, const float* __restrict__ WrIU,
                          const float* __restrict__ WlUI, const float* __restrict__ WrUI,
                          const float* __restrict__ Wuser, const float* __restrict__ Witem) {
    int row = blockIdx.x;
    int mat = blockIdx.y;
    int j = threadIdx.x;
    const float* L; const float* R;
    if (mat == 0)      { L = WlIU; R = Wuser; }
    else if (mat == 1) { L = WrIU; R = Wuser; }
    else if (mat == 2) { L = WlUI; R = Witem; }
    else               { L = WrUI; R = Witem; }
    float s = 0.f;
#pragma unroll 8
    for (int k = 0; k < 128; k++) s += L[row * 128 + k] * R[k * 128 + j];
    int gk = (mat & 1) ? (128 + row) : row;
    __nv_bfloat16* Th = (mat < 2) ? g_WuT_hi : g_WiT_hi;
    __nv_bfloat16* Tl = (mat < 2) ? g_WuT_lo : g_WiT_lo;
    __nv_bfloat16 h = __float2bfloat16_rn(s);
    float r = s - __bfloat162float(h);
    Th[(size_t)j * 256 + gk] = h;
    Tl[(size_t)j * 256 + gk] = __float2bfloat16_rn(r);
}

__global__ void combine_c(const float* __restrict__ blIU, const float* __restrict__ bUser,
                          const float* __restrict__ blUI, const float* __restrict__ bItem,
                          const float* __restrict__ Wuser, const float* __restrict__ Witem) {
    int j = threadIdx.x;
    if (blockIdx.x == 0) {
        float s = bUser[j];
#pragma unroll 8
        for (int k = 0; k < 128; k++) s += blIU[k] * Wuser[k * 128 + j];
        g_cu[j] = s;
    } else {
        float s = bItem[j];
#pragma unroll 8
        for (int k = 0; k < 128; k++) s += blUI[k] * Witem[k * 128 + j];
        g_ci[j] = s;
    }
}

// ---------------- mma.sync node GEMM: 3-region smem, agg in fp16 ----------------
// R0 = A (bf16 hi at +0, lo at +16384, swizzled). R1 = B (hi/lo). R2 = staging
// (fp16 agg rows 128x256B, or fp32 x chunk 128x256B).
#define RG0 0u
#define RG1 32768u
#define RG2 65536u
#define SM_TOTAL 98304u

__device__ __forceinline__ void ldsm4(uint32_t& r0, uint32_t& r1, uint32_t& r2, uint32_t& r3,
                                      uint32_t addr) {
    asm volatile("ldmatrix.sync.aligned.m8n8.x4.shared.b16 {%0,%1,%2,%3}, [%4];"
                 : "=r"(r0), "=r"(r1), "=r"(r2), "=r"(r3) : "r"(addr));
}
__device__ __forceinline__ void mma16816(float* c, uint32_t a0, uint32_t a1, uint32_t a2,
                                         uint32_t a3, uint32_t b0, uint32_t b1) {
    asm volatile("mma.sync.aligned.m16n8k16.row.col.f32.bf16.bf16.f32 "
                 "{%0,%1,%2,%3}, {%4,%5,%6,%7}, {%8,%9}, {%0,%1,%2,%3};"
                 : "+f"(c[0]), "+f"(c[1]), "+f"(c[2]), "+f"(c[3])
                 : "r"(a0), "r"(a1), "r"(a2), "r"(a3), "r"(b0), "r"(b1));
}

__global__ __launch_bounds__(256, 2)
void node_gemm_mma(const __half* __restrict__ aggf,
                   const float* __restrict__ xself,
                   const __nv_bfloat16* __restrict__ WTh, const __nv_bfloat16* __restrict__ WTl,
                   const float* __restrict__ cvec, float* __restrict__ out, int M) {
    extern __shared__ char smem[];
    const uint32_t sb = smem_u32(smem);
    const int tid = threadIdx.x;
    const int wid = tid >> 5;
    const int lane = tid & 31;
    const int rowBase = blockIdx.x * 128;

    const int mw = wid & 1;
    const int nw = wid >> 1;

    const int laneRowA = mw * 64 + (lane & 15);
    const uint32_t cAxor = (uint32_t)(laneRowA & 7) << 4;
    const uint32_t aRowByte = (uint32_t)laneRowA * 128;
    const uint32_t kLaneByte = (uint32_t)(lane >> 4) * 16;

    uint32_t bRowByte[2], cBxor[2];
#pragma unroll
    for (int nt2 = 0; nt2 < 2; nt2++) {
        int rn = nw * 32 + nt2 * 16 + (lane & 15);
        bRowByte[nt2] = (uint32_t)rn * 128;
        cBxor[nt2] = (uint32_t)(rn & 7) << 4;
    }

    float acc[4][4][4];
#pragma unroll
    for (int i = 0; i < 4; i++)
#pragma unroll
        for (int j = 0; j < 4; j++)
#pragma unroll
            for (int r = 0; r < 4; r++) acc[i][j][r] = 0.f;

    auto stageB = [&](int cK) {
#pragma unroll
        for (int i = 0; i < 4; i++) {
            int g = tid + i * 256;
            int row = g >> 3, k8 = (g & 7) * 8;
            uint32_t sw = (uint32_t)row * 128 + (((uint32_t)k8 * 2) ^ ((uint32_t)(row & 7) << 4));
            cpa16(sb + RG1 + sw, WTh + (size_t)row * 256 + cK + k8);
            cpa16(sb + RG1 + 16384u + sw, WTl + (size_t)row * 256 + cK + k8);
        }
        CP_COMMIT();
    };
    // stage 128 rows x 256B of fp16 agg into R2 (linear)
    auto stage_aggf = [&]() {
#pragma unroll
        for (int i = 0; i < 8; i++) {
            int c = tid + i * 256;        // 0..2047 16B chunks
            int row = c >> 4;             // 16 chunks (256B) per row
            int c16 = c & 15;
            int gr = rowBase + row;
            uint32_t d = RG2 + (uint32_t)row * 256 + (uint32_t)c16 * 16;
            if (gr < M) {
                cpa16(sb + d, reinterpret_cast<const char*>(aggf) + (size_t)gr * 256 + c16 * 16);
            } else {
                *reinterpret_cast<uint4*>(smem + d) = make_uint4(0, 0, 0, 0);
            }
        }
        CP_COMMIT();
    };
    // stage 128x64 fp32 xself chunk into R2 (linear)
    auto stage_x = [&](int koff) {
#pragma unroll
        for (int i = 0; i < 8; i++) {
            int c = tid + i * 256;
            int row = c >> 4;
            int k16 = c & 15;
            int gr = rowBase + row;
            uint32_t d = RG2 + (uint32_t)row * 256 + (uint32_t)k16 * 16;
            if (gr < M) {
                cpa16(sb + d, xself + (size_t)gr * 128 + koff + k16 * 4);
            } else {
                *reinterpret_cast<uint4*>(smem + d) = make_uint4(0, 0, 0, 0);
            }
        }
        CP_COMMIT();
    };
    // convert fp16 agg (R2 linear) chunk koff -> bf16 hi/lo swizzled at R0
    auto convert_agg = [&](int koff) {
#pragma unroll
        for (int i = 0; i < 4; i++) {
            int g = tid + i * 256;
            int row = g >> 3, k8 = (g & 7) * 8;
            uint4 hv = *reinterpret_cast<const uint4*>(smem + RG2 + row * 256 + (koff + k8) * 2);
            const __half* hp = reinterpret_cast<const __half*>(&hv);
            uint32_t hw[4], lw[4];
#pragma unroll
            for (int j = 0; j < 4; j++) {
                float a = __half2float(hp[2 * j]);
                float b = __half2float(hp[2 * j + 1]);
                __nv_bfloat16 h0 = __float2bfloat16_rn(a);
                __nv_bfloat16 h1 = __float2bfloat16_rn(b);
                __nv_bfloat162 hpk; hpk.x = h0; hpk.y = h1;
                hw[j] = *reinterpret_cast<uint32_t*>(&hpk);
                lw[j] = packbf2(a - __bfloat162float(h0), b - __bfloat162float(h1));
            }
            uint32_t sw = (uint32_t)row * 128 + (((uint32_t)k8 * 2) ^ ((uint32_t)(row & 7) << 4));
            *reinterpret_cast<uint4*>(smem + RG0 + sw) = make_uint4(hw[0], hw[1], hw[2], hw[3]);
            *reinterpret_cast<uint4*>(smem + RG0 + 16384u + sw) = make_uint4(lw[0], lw[1], lw[2], lw[3]);
        }
    };
    // convert fp32 x (R2 linear, 64-wide chunk) -> bf16 hi/lo swizzled at R0
    auto convert_x = [&]() {
#pragma unroll
        for (int i = 0; i < 4; i++) {
            int g = tid + i * 256;
            int row = g >> 3, k8 = (g & 7) * 8;
            float4 f0 = *reinterpret_cast<const float4*>(smem + RG2 + row * 256 + k8 * 4);
            float4 f1 = *reinterpret_cast<const float4*>(smem + RG2 + row * 256 + k8 * 4 + 16);
            uint32_t hw[4], lw[4];
            float v[8] = {f0.x, f0.y, f0.z, f0.w, f1.x, f1.y, f1.z, f1.w};
#pragma unroll
            for (int j = 0; j < 4; j++) {
                float a = v[2 * j], b = v[2 * j + 1];
                __nv_bfloat16 h0 = __float2bfloat16_rn(a);
                __nv_bfloat16 h1 = __float2bfloat16_rn(b);
                __nv_bfloat162 hp; hp.x = h0; hp.y = h1;
                hw[j] = *reinterpret_cast<uint32_t*>(&hp);
                lw[j] = packbf2(a - __bfloat162float(h0), b - __bfloat162float(h1));
            }
            uint32_t sw = (uint32_t)row * 128 + (((uint32_t)k8 * 2) ^ ((uint32_t)(row & 7) << 4));
            *reinterpret_cast<uint4*>(smem + RG0 + sw) = make_uint4(hw[0], hw[1], hw[2], hw[3]);
            *reinterpret_cast<uint4*>(smem + RG0 + 16384u + sw) = make_uint4(lw[0], lw[1], lw[2], lw[3]);
        }
    };
    auto compute = [&]() {
#pragma unroll
        for (int ks = 0; ks < 4; ks++) {
            uint32_t kb = (uint32_t)ks * 32 + kLaneByte;
            uint32_t bh[4][2], bl[4][2];
#pragma unroll
            for (int nt2 = 0; nt2 < 2; nt2++) {
                uint32_t r0, r1, r2, r3;
                ldsm4(r0, r1, r2, r3, sb + RG1 + bRowByte[nt2] + (kb ^ cBxor[nt2]));
                bh[nt2 * 2][0] = r0; bh[nt2 * 2][1] = r2;
                bh[nt2 * 2 + 1][0] = r1; bh[nt2 * 2 + 1][1] = r3;
                ldsm4(r0, r1, r2, r3, sb + RG1 + 16384u + bRowByte[nt2] + (kb ^ cBxor[nt2]));
                bl[nt2 * 2][0] = r0; bl[nt2 * 2][1] = r2;
                bl[nt2 * 2 + 1][0] = r1; bl[nt2 * 2 + 1][1] = r3;
            }
#pragma unroll
            for (int mt = 0; mt < 4; mt++) {
                uint32_t ah0, ah1, ah2, ah3, al0, al1, al2, al3;
                uint32_t abase = sb + RG0 + aRowByte + (uint32_t)mt * 2048 + (kb ^ cAxor);
                ldsm4(ah0, ah1, ah2, ah3, abase);
                ldsm4(al0, al1, al2, al3, abase + 16384u);
#pragma unroll
                for (int nt = 0; nt < 4; nt++) {
                    mma16816(acc[mt][nt], ah0, ah1, ah2, ah3, bh[nt][0], bh[nt][1]);
                    mma16816(acc[mt][nt], ah0, ah1, ah2, ah3, bl[nt][0], bl[nt][1]);
                    mma16816(acc[mt][nt], al0, al1, al2, al3, bh[nt][0], bh[nt][1]);
                }
            }
        }
    };

    // chunk0: agg k0
    stage_aggf();
    stageB(0);
    CP_WAIT0();
    __syncthreads();          // all threads' staged R2/B visible
    convert_agg(0);
    __syncthreads();
    compute();
    __syncthreads();
    // chunk1: agg k64 (R2 still holds full agg rows)
    stageB(64);
    convert_agg(64);
    CP_WAIT0();
    __syncthreads();
    compute();
    __syncthreads();
    // chunk2: x k0
    stage_x(0);
    stageB(128);
    CP_WAIT0();
    __syncthreads();          // FIX: make other threads' cp.async R2 data visible
    convert_x();
    __syncthreads();
    compute();
    __syncthreads();
    // chunk3: x k64
    stage_x(64);
    stageB(192);
    CP_WAIT0();
    __syncthreads();          // FIX: same
    convert_x();
    __syncthreads();
    compute();

    // ---- epilogue ----
    float cb[4][2];
#pragma unroll
    for (int nt = 0; nt < 4; nt++) {
        int col = nw * 32 + nt * 8 + (lane & 3) * 2;
        cb[nt][0] = __ldg(cvec + col);
        cb[nt][1] = __ldg(cvec + col + 1);
    }
#pragma unroll
    for (int mt = 0; mt < 4; mt++) {
        int r0 = rowBase + mw * 64 + mt * 16 + (lane >> 2);
        int r1 = r0 + 8;
#pragma unroll
        for (int nt = 0; nt < 4; nt++) {
            int col = nw * 32 + nt * 8 + (lane & 3) * 2;
            if (r0 < M) {
                float2 o;
                o.x = fmaxf(acc[mt][nt][0] + cb[nt][0], 0.f);
                o.y = fmaxf(acc[mt][nt][1] + cb[nt][1], 0.f);
                *reinterpret_cast<float2*>(out + (size_t)r0 * 128 + col) = o;
            }
            if (r1 < M) {
                float2 o;
                o.x = fmaxf(acc[mt][nt][2] + cb[nt][0], 0.f);
                o.y = fmaxf(acc[mt][nt][3] + cb[nt][1], 0.f);
                *reinterpret_cast<float2*>(out + (size_t)r1 * 128 + col) = o;
            }
        }
    }
}

// ---------------- host launch (R13 topology: item chain on s2) ----------------
extern "C" void kernel_launch(void* const* d_in, const int* in_sizes, int n_in,
                              void* d_out, int out_size) {
    const float* x_user = (const float*)d_in[0];
    const float* x_item = (const float*)d_in[1];
    const int* esrc_ui = (const int*)d_in[2];
    const int* edst_ui = (const int*)d_in[3];
    const int* esrc_iu = (const int*)d_in[4];
    const int* edst_iu = (const int*)d_in[5];
    const float* Wl_ui = (const float*)d_in[6];
    const float* bl_ui = (const float*)d_in[7];
    const float* Wr_ui = (const float*)d_in[8];
    const float* Wl_iu = (const float*)d_in[9];
    const float* bl_iu = (const float*)d_in[10];
    const float* Wr_iu = (const float*)d_in[11];
    const float* W_user = (const float*)d_in[12];
    const float* b_user = (const float*)d_in[13];
    const float* W_item = (const float*)d_in[14];
    const float* b_item = (const float*)d_in[15];
    float* out = (float*)d_out;

    int ne_ui = in_sizes[2];
    int ne_iu = in_sizes[4];
    int totE = ne_ui + ne_iu;

    void *p_aggf, *p_Wuh, *p_Wul, *p_Wih, *p_Wil, *p_cu, *p_ci, *p_cnt, *p_desc;
    cudaGetSymbolAddress(&p_aggf, g_aggf);
    cudaGetSymbolAddress(&p_Wuh, g_WuT_hi);
    cudaGetSymbolAddress(&p_Wul, g_WuT_lo);
    cudaGetSymbolAddress(&p_Wih, g_WiT_hi);
    cudaGetSymbolAddress(&p_Wil, g_WiT_lo);
    cudaGetSymbolAddress(&p_cu, g_cu);
    cudaGetSymbolAddress(&p_ci, g_ci);
    cudaGetSymbolAddress(&p_cnt, g_cnt);
    cudaGetSymbolAddress(&p_desc, (const void*)g_blkDesc);

    cudaFuncSetAttribute(node_gemm_mma, cudaFuncAttributeMaxDynamicSharedMemorySize, SM_TOTAL);

    static cudaStream_t s2 = nullptr;
    static cudaEvent_t evStart = nullptr, evComb = nullptr, evFill = nullptr, evDone = nullptr;
    if (s2 == nullptr) {
        cudaStreamCreateWithFlags(&s2, cudaStreamNonBlocking);
        cudaEventCreateWithFlags(&evStart, cudaEventDisableTiming);
        cudaEventCreateWithFlags(&evComb, cudaEventDisableTiming);
        cudaEventCreateWithFlags(&evFill, cudaEventDisableTiming);
        cudaEventCreateWithFlags(&evDone, cudaEventDisableTiming);
    }

    // fork s2 from the (capturing) default stream
    cudaEventRecord(evStart, 0);
    cudaStreamWaitEvent(s2, evStart, 0);

    // s2: weight combines (independent of CSR)
    combine_w<<<dim3(128, 4), 128, 0, s2>>>(Wl_iu, Wr_iu, Wl_ui, Wr_ui, W_user, W_item);
    combine_c<<<2, 128, 0, s2>>>(bl_iu, b_user, bl_ui, b_item, W_user, W_item);
    cudaEventRecord(evComb, s2);

    // main: CSR build (memset + hist + single-pass scan + fill)
    cudaMemsetAsync(p_cnt, 0, (size_t)NT * sizeof(int), 0);
    cudaMemsetAsync(p_desc, 0, 512 * sizeof(long long), 0);
    hist_all<<<(totE + 255) / 256, 256>>>(edst_iu, ne_iu, edst_ui, ne_ui);
    scan_chained<<<NBLK, 1024>>>(totE);
    fill_all<<<(totE + 255) / 256, 256>>>(esrc_iu, edst_iu, ne_iu, esrc_ui, edst_ui, ne_ui);
    cudaEventRecord(evFill, 0);

    // s2: full item chain — gather then GEMM (co-runs with user chain on main)
    cudaStreamWaitEvent(s2, evFill, 0);
    gather_part<<<(NII * 32 + 255) / 256, 256, 0, s2>>>(x_user, NUU, NT);
    node_gemm_mma<<<(NII + 127) / 128, 256, SM_TOTAL, s2>>>(
        (const __half*)p_aggf + (size_t)NUU * 128, x_item,
        (const __nv_bfloat16*)p_Wih, (const __nv_bfloat16*)p_Wil,
        (const float*)p_ci, out + (size_t)NUU * 128, NII);
    cudaEventRecord(evDone, s2);

    // main: user gather, then user GEMM (after combines)
    gather_part<<<(NUU * 32 + 255) / 256, 256>>>(x_item, 0, NUU);
    cudaStreamWaitEvent(0, evComb, 0);
    node_gemm_mma<<<(NUU + 127) / 128, 256, SM_TOTAL>>>(
        (const __half*)p_aggf, x_user,
        (const __nv_bfloat16*)p_Wuh, (const __nv_bfloat16*)p_Wul,
        (const float*)p_cu, out, NUU);

    // join item chain back into the captured stream
    cudaStreamWaitEvent(0, evDone, 0);
}

// round 17
// speedup vs baseline: 1.2110x; 1.2110x over previous
#include <cuda_runtime.h>
#include <cuda_fp16.h>
#include <cstdint>

#define NUU 200000
#define NII 100000
#define NT  (NUU + NII)
#define NBLK ((NT + 1023) / 1024)   // 293

// ---------------- scratch (static device globals; no allocation) ----------------
// agg: per node 128 fp16 (256B), PRE-SWIZZLED per 128B half-row:
// byte offset = (kin*2) ^ ((node&7)<<4).
__device__ __half g_aggf[(size_t)NT * 128];
__device__ int g_cnt[NT];
__device__ int g_off[NT + 1];
__device__ int g_cur[NT];
__device__ volatile long long g_blkDesc[512];   // (value<<2)|state ; 0=inv,1=agg,2=prefix
__device__ int g_nbr[1200000 + 64];
// combined weights, transposed to [N=128][K=256], fp16 hi/lo
__device__ __half g_WuT_hi[128 * 256];
__device__ __half g_WuT_lo[128 * 256];
__device__ __half g_WiT_hi[128 * 256];
__device__ __half g_WiT_lo[128 * 256];
__device__ float g_cu[128];
__device__ float g_ci[128];

__device__ __forceinline__ uint32_t smem_u32(const void* p) {
    uint32_t a;
    asm("{ .reg .u64 t; cvta.to.shared.u64 t, %1; cvt.u32.u64 %0, t; }" : "=r"(a) : "l"(p));
    return a;
}
__device__ __forceinline__ void cpa16(uint32_t d, const void* s) {
    asm volatile("cp.async.cg.shared.global [%0], [%1], 16;" :: "r"(d), "l"(s));
}
#define CP_COMMIT() asm volatile("cp.async.commit_group;" ::: "memory")
#define CP_WAIT0()  asm volatile("cp.async.wait_group 0;" ::: "memory")

// ---------------- CSR build ----------------
__global__ void hist_all(const int* __restrict__ diu, int neiu,
                         const int* __restrict__ dui, int neui) {
    int i = blockIdx.x * blockDim.x + threadIdx.x;
    if (i < neiu) atomicAdd(&g_cnt[diu[i]], 1);
    else if (i < neiu + neui) atomicAdd(&g_cnt[NUU + dui[i - neiu]], 1);
}

// one-pass decoupled-lookback exclusive scan of g_cnt -> g_off/g_cur
__global__ void scan_chained(int totE) {
    __shared__ int sh[1024];
    __shared__ int s_pref;
    int t = threadIdx.x;
    int b = blockIdx.x;
    int idx = b * 1024 + t;
    int c = (idx < NT) ? g_cnt[idx] : 0;
    sh[t] = c;
    __syncthreads();
#pragma unroll
    for (int o = 1; o < 1024; o <<= 1) {
        int v = (t >= o) ? sh[t - o] : 0;
        __syncthreads();
        sh[t] += v;
        __syncthreads();
    }
    int total = sh[1023];

    if (b == 0) {
        if (t == 0) {
            s_pref = 0;
            g_blkDesc[0] = ((long long)total << 2) | 2;
        }
        __syncthreads();
    } else {
        if (t == 0)
            g_blkDesc[b] = ((long long)total << 2) | 1;
        if (t < 32) {
            int lane = t;
            int run = 0;
            int look = b - 1;
            while (true) {
                int ix = look - lane;
                int st, val;
                if (ix >= 0) {
                    long long d;
                    do { d = g_blkDesc[ix]; } while ((d & 3) == 0);
                    st = (int)(d & 3);
                    val = (int)(d >> 2);
                } else { st = 2; val = 0; }
                unsigned mask = __ballot_sync(0xffffffffu, st == 2);
                int firstLane = mask ? (__ffs(mask) - 1) : 32;
                int contrib = (lane <= firstLane) ? val : 0;
#pragma unroll
                for (int o = 16; o > 0; o >>= 1)
                    contrib += __shfl_xor_sync(0xffffffffu, contrib, o);
                run += contrib;
                if (mask) break;
                look -= 32;
            }
            if (lane == 0) {
                s_pref = run;
                g_blkDesc[b] = ((long long)(run + total) << 2) | 2;
            }
        }
        __syncthreads();
    }

    if (idx < NT) {
        int v = s_pref + sh[t] - c;
        g_off[idx] = v;
        g_cur[idx] = v;
    }
    if (idx == 0) g_off[NT] = totE;
}

__global__ void fill_all(const int* __restrict__ siu, const int* __restrict__ diu, int neiu,
                         const int* __restrict__ sui, const int* __restrict__ dui, int neui) {
    int i = blockIdx.x * blockDim.x + threadIdx.x;
    if (i < neiu) {
        int p = atomicAdd(&g_cur[diu[i]], 1);
        g_nbr[p] = siu[i];
    } else if (i < neiu + neui) {
        int j = i - neiu;
        int p = atomicAdd(&g_cur[NUU + dui[j]], 1);
        g_nbr[p] = sui[j];
    }
}

__device__ __forceinline__ uint32_t packh2(float a, float b) {
    __half2 p;
    p.x = __float2half_rn(a);
    p.y = __float2half_rn(b);
    return *reinterpret_cast<uint32_t*>(&p);
}

// ---------------- gather: one warp per dst node; mean -> fp16, pre-swizzled ----------------
__global__ void gather_part(const float* __restrict__ xs, int nodeBeg, int nodeEnd) {
    int w = nodeBeg + ((blockIdx.x * blockDim.x + threadIdx.x) >> 5);
    int lane = threadIdx.x & 31;
    if (w >= nodeEnd) return;
    int o = g_off[w], e = g_off[w + 1];
    float a0 = 0.f, a1 = 0.f, a2 = 0.f, a3 = 0.f;
    int kk = lane * 4;
    int p = o;
    for (; p + 3 < e; p += 4) {
        int s0 = __ldg(&g_nbr[p]);
        int s1 = __ldg(&g_nbr[p + 1]);
        int s2 = __ldg(&g_nbr[p + 2]);
        int s3 = __ldg(&g_nbr[p + 3]);
        float4 v0 = *reinterpret_cast<const float4*>(xs + (size_t)s0 * 128 + kk);
        float4 v1 = *reinterpret_cast<const float4*>(xs + (size_t)s1 * 128 + kk);
        float4 v2 = *reinterpret_cast<const float4*>(xs + (size_t)s2 * 128 + kk);
        float4 v3 = *reinterpret_cast<const float4*>(xs + (size_t)s3 * 128 + kk);
        a0 += (v0.x + v1.x) + (v2.x + v3.x);
        a1 += (v0.y + v1.y) + (v2.y + v3.y);
        a2 += (v0.z + v1.z) + (v2.z + v3.z);
        a3 += (v0.w + v1.w) + (v2.w + v3.w);
    }
    if (p + 1 < e) {
        int s0 = __ldg(&g_nbr[p]);
        int s1 = __ldg(&g_nbr[p + 1]);
        float4 v0 = *reinterpret_cast<const float4*>(xs + (size_t)s0 * 128 + kk);
        float4 v1 = *reinterpret_cast<const float4*>(xs + (size_t)s1 * 128 + kk);
        a0 += v0.x + v1.x; a1 += v0.y + v1.y; a2 += v0.z + v1.z; a3 += v0.w + v1.w;
        p += 2;
    }
    if (p < e) {
        int s0 = __ldg(&g_nbr[p]);
        float4 v0 = *reinterpret_cast<const float4*>(xs + (size_t)s0 * 128 + kk);
        a0 += v0.x; a1 += v0.y; a2 += v0.z; a3 += v0.w;
    }
    float inv = 1.0f / (float)max(e - o, 1);
    a0 *= inv; a1 *= inv; a2 *= inv; a3 *= inv;
    uint2 hv = make_uint2(packh2(a0, a1), packh2(a2, a3));
    // pre-swizzled store: half-row = kk>=64; within 128B: (kin*2)^((w&7)<<4)
    int kin = kk & 63;
    uint32_t off = ((uint32_t)(kin * 2)) ^ (((uint32_t)w & 7u) << 4);
    size_t base = (size_t)w * 256 + ((kk >> 6) ? 128u : 0u) + off;
    *reinterpret_cast<uint2*>(reinterpret_cast<char*>(g_aggf) + base) = hv;
}

// ---------------- combine weights: O = L @ R, transposed fp16 hi/lo ----------------
__global__ void combine_w(const float* __restrict__ WlIU, const float* __restrict__ WrIU,
                          const float* __restrict__ WlUI, const float* __restrict__ WrUI,
                          const float* __restrict__ Wuser, const float* __restrict__ Witem) {
    int row = blockIdx.x;
    int mat = blockIdx.y;
    int j = threadIdx.x;
    const float* L; const float* R;
    if (mat == 0)      { L = WlIU; R = Wuser; }
    else if (mat == 1) { L = WrIU; R = Wuser; }
    else if (mat == 2) { L = WlUI; R = Witem; }
    else               { L = WrUI; R = Witem; }
    float s = 0.f;
#pragma unroll 8
    for (int k = 0; k < 128; k++) s += L[row * 128 + k] * R[k * 128 + j];
    int gk = (mat & 1) ? (128 + row) : row;
    __half* Th = (mat < 2) ? g_WuT_hi : g_WiT_hi;
    __half* Tl = (mat < 2) ? g_WuT_lo : g_WiT_lo;
    __half h = __float2half_rn(s);
    float r = s - __half2float(h);
    Th[(size_t)j * 256 + gk] = h;
    Tl[(size_t)j * 256 + gk] = __float2half_rn(r);
}

__global__ void combine_c(const float* __restrict__ blIU, const float* __restrict__ bUser,
                          const float* __restrict__ blUI, const float* __restrict__ bItem,
                          const float* __restrict__ Wuser, const float* __restrict__ Witem) {
    int j = threadIdx.x;
    if (blockIdx.x == 0) {
        float s = bUser[j];
#pragma unroll 8
        for (int k = 0; k < 128; k++) s += blIU[k] * Wuser[k * 128 + j];
        g_cu[j] = s;
    } else {
        float s = bItem[j];
#pragma unroll 8
        for (int k = 0; k < 128; k++) s += blUI[k] * Witem[k * 128 + j];
        g_ci[j] = s;
    }
}

// ---------------- fp16 mma.sync node GEMM ----------------
// A: 16KB fp16 swizzled (128 rows x 128B per 64-k chunk).
// B: 32KB (wh at +0, wl at +16384), swizzled.
// X: 32KB fp32 staging (linear, 128 rows x 256B).
#define RG_A 0u
#define RG_B 16384u
#define RG_X 49152u
#define SM_TOTAL 81920u

__device__ __forceinline__ void ldsm4(uint32_t& r0, uint32_t& r1, uint32_t& r2, uint32_t& r3,
                                      uint32_t addr) {
    asm volatile("ldmatrix.sync.aligned.m8n8.x4.shared.b16 {%0,%1,%2,%3}, [%4];"
                 : "=r"(r0), "=r"(r1), "=r"(r2), "=r"(r3) : "r"(addr));
}
__device__ __forceinline__ void mma16816h(float* c, uint32_t a0, uint32_t a1, uint32_t a2,
                                          uint32_t a3, uint32_t b0, uint32_t b1) {
    asm volatile("mma.sync.aligned.m16n8k16.row.col.f32.f16.f16.f32 "
                 "{%0,%1,%2,%3}, {%4,%5,%6,%7}, {%8,%9}, {%0,%1,%2,%3};"
                 : "+f"(c[0]), "+f"(c[1]), "+f"(c[2]), "+f"(c[3])
                 : "r"(a0), "r"(a1), "r"(a2), "r"(a3), "r"(b0), "r"(b1));
}

__global__ __launch_bounds__(256, 2)
void node_gemm_mma(const __half* __restrict__ aggf,
                   const float* __restrict__ xself,
                   const __half* __restrict__ WTh, const __half* __restrict__ WTl,
                   const float* __restrict__ cvec, float* __restrict__ out, int M) {
    extern __shared__ char smem[];
    const uint32_t sb = smem_u32(smem);
    const int tid = threadIdx.x;
    const int wid = tid >> 5;
    const int lane = tid & 31;
    const int rowBase = blockIdx.x * 128;

    const int mw = wid & 1;
    const int nw = wid >> 1;

    const int laneRowA = mw * 64 + (lane & 15);
    const uint32_t cAxor = (uint32_t)(laneRowA & 7) << 4;
    const uint32_t aRowByte = (uint32_t)laneRowA * 128;
    const uint32_t kLaneByte = (uint32_t)(lane >> 4) * 16;

    uint32_t bRowByte[2], cBxor[2];
#pragma unroll
    for (int nt2 = 0; nt2 < 2; nt2++) {
        int rn = nw * 32 + nt2 * 16 + (lane & 15);
        bRowByte[nt2] = (uint32_t)rn * 128;
        cBxor[nt2] = (uint32_t)(rn & 7) << 4;
    }

    float acc[4][4][4];
#pragma unroll
    for (int i = 0; i < 4; i++)
#pragma unroll
        for (int j = 0; j < 4; j++)
#pragma unroll
            for (int r = 0; r < 4; r++) acc[i][j][r] = 0.f;

    auto stageB = [&](int cK) {
#pragma unroll
        for (int i = 0; i < 4; i++) {
            int g = tid + i * 256;
            int row = g >> 3, k8 = (g & 7) * 8;
            uint32_t sw = (uint32_t)row * 128 + (((uint32_t)k8 * 2) ^ ((uint32_t)(row & 7) << 4));
            cpa16(sb + RG_B + sw, WTh + (size_t)row * 256 + cK + k8);
            cpa16(sb + RG_B + 16384u + sw, WTl + (size_t)row * 256 + cK + k8);
        }
        CP_COMMIT();
    };
    // agg chunk (half = 0 or 128 bytes): pure swizzled 16B copies into A
    auto stageA_agg = [&](uint32_t half) {
        const char* ph = reinterpret_cast<const char*>(aggf);
#pragma unroll
        for (int i = 0; i < 4; i++) {
            int c = tid + i * 256;        // 0..1023
            int row = c >> 3;             // 0..127
            uint32_t c16 = (uint32_t)(c & 7) * 16;
            int gr = rowBase + row;
            uint32_t d = RG_A + (uint32_t)row * 128 + c16;
            if (gr < M) {
                cpa16(sb + d, ph + (size_t)gr * 256 + half + c16);
            } else {
                *reinterpret_cast<uint4*>(smem + d) = make_uint4(0, 0, 0, 0);
            }
        }
        CP_COMMIT();
    };
    // stage 128x64 fp32 xself chunk into X (linear)
    auto stage_x = [&](int koff) {
#pragma unroll
        for (int i = 0; i < 8; i++) {
            int c = tid + i * 256;
            int row = c >> 4;
            int k16 = c & 15;
            int gr = rowBase + row;
            uint32_t d = RG_X + (uint32_t)row * 256 + (uint32_t)k16 * 16;
            if (gr < M) {
                cpa16(sb + d, xself + (size_t)gr * 128 + koff + k16 * 4);
            } else {
                *reinterpret_cast<uint4*>(smem + d) = make_uint4(0, 0, 0, 0);
            }
        }
        CP_COMMIT();
    };
    // convert fp32 x (X linear) -> fp16 swizzled at A
    auto convert_x = [&]() {
#pragma unroll
        for (int i = 0; i < 4; i++) {
            int g = tid + i * 256;
            int row = g >> 3, k8 = (g & 7) * 8;
            float4 f0 = *reinterpret_cast<const float4*>(smem + RG_X + row * 256 + k8 * 4);
            float4 f1 = *reinterpret_cast<const float4*>(smem + RG_X + row * 256 + k8 * 4 + 16);
            uint4 hv = make_uint4(packh2(f0.x, f0.y), packh2(f0.z, f0.w),
                                  packh2(f1.x, f1.y), packh2(f1.z, f1.w));
            uint32_t sw = (uint32_t)row * 128 + (((uint32_t)k8 * 2) ^ ((uint32_t)(row & 7) << 4));
            *reinterpret_cast<uint4*>(smem + RG_A + sw) = hv;
        }
    };
    auto compute = [&]() {
#pragma unroll
        for (int ks = 0; ks < 4; ks++) {
            uint32_t kb = (uint32_t)ks * 32 + kLaneByte;
            uint32_t bh[4][2], bl[4][2];
#pragma unroll
            for (int nt2 = 0; nt2 < 2; nt2++) {
                uint32_t r0, r1, r2, r3;
                ldsm4(r0, r1, r2, r3, sb + RG_B + bRowByte[nt2] + (kb ^ cBxor[nt2]));
                bh[nt2 * 2][0] = r0; bh[nt2 * 2][1] = r2;
                bh[nt2 * 2 + 1][0] = r1; bh[nt2 * 2 + 1][1] = r3;
                ldsm4(r0, r1, r2, r3, sb + RG_B + 16384u + bRowByte[nt2] + (kb ^ cBxor[nt2]));
                bl[nt2 * 2][0] = r0; bl[nt2 * 2][1] = r2;
                bl[nt2 * 2 + 1][0] = r1; bl[nt2 * 2 + 1][1] = r3;
            }
#pragma unroll
            for (int mt = 0; mt < 4; mt++) {
                uint32_t a0, a1, a2, a3;
                ldsm4(a0, a1, a2, a3,
                      sb + RG_A + aRowByte + (uint32_t)mt * 2048 + (kb ^ cAxor));
#pragma unroll
                for (int nt = 0; nt < 4; nt++) {
                    mma16816h(acc[mt][nt], a0, a1, a2, a3, bh[nt][0], bh[nt][1]);
                    mma16816h(acc[mt][nt], a0, a1, a2, a3, bl[nt][0], bl[nt][1]);
                }
            }
        }
    };

    // chunk0: agg k0
    stageA_agg(0);
    stageB(0);
    CP_WAIT0();
    __syncthreads();
    compute();
    __syncthreads();
    // chunk1: agg k64
    stageA_agg(128);
    stageB(64);
    CP_WAIT0();
    __syncthreads();
    compute();
    __syncthreads();
    // chunk2: x k0
    stage_x(0);
    stageB(128);
    CP_WAIT0();
    __syncthreads();
    convert_x();
    __syncthreads();
    compute();
    __syncthreads();
    // chunk3: x k64
    stage_x(64);
    stageB(192);
    CP_WAIT0();
    __syncthreads();
    convert_x();
    __syncthreads();
    compute();

    // ---- epilogue ----
    float cb[4][2];
#pragma unroll
    for (int nt = 0; nt < 4; nt++) {
        int col = nw * 32 + nt * 8 + (lane & 3) * 2;
        cb[nt][0] = __ldg(cvec + col);
        cb[nt][1] = __ldg(cvec + col + 1);
    }
#pragma unroll
    for (int mt = 0; mt < 4; mt++) {
        int r0 = rowBase + mw * 64 + mt * 16 + (lane >> 2);
        int r1 = r0 + 8;
#pragma unroll
        for (int nt = 0; nt < 4; nt++) {
            int col = nw * 32 + nt * 8 + (lane & 3) * 2;
            if (r0 < M) {
                float2 o;
                o.x = fmaxf(acc[mt][nt][0] + cb[nt][0], 0.f);
                o.y = fmaxf(acc[mt][nt][1] + cb[nt][1], 0.f);
                *reinterpret_cast<float2*>(out + (size_t)r0 * 128 + col) = o;
            }
            if (r1 < M) {
                float2 o;
                o.x = fmaxf(acc[mt][nt][2] + cb[nt][0], 0.f);
                o.y = fmaxf(acc[mt][nt][3] + cb[nt][1], 0.f);
                *reinterpret_cast<float2*>(out + (size_t)r1 * 128 + col) = o;
            }
        }
    }
}

// ---------------- host launch (R13 topology: item chain on s2) ----------------
extern "C" void kernel_launch(void* const* d_in, const int* in_sizes, int n_in,
                              void* d_out, int out_size) {
    const float* x_user = (const float*)d_in[0];
    const float* x_item = (const float*)d_in[1];
    const int* esrc_ui = (const int*)d_in[2];
    const int* edst_ui = (const int*)d_in[3];
    const int* esrc_iu = (const int*)d_in[4];
    const int* edst_iu = (const int*)d_in[5];
    const float* Wl_ui = (const float*)d_in[6];
    const float* bl_ui = (const float*)d_in[7];
    const float* Wr_ui = (const float*)d_in[8];
    const float* Wl_iu = (const float*)d_in[9];
    const float* bl_iu = (const float*)d_in[10];
    const float* Wr_iu = (const float*)d_in[11];
    const float* W_user = (const float*)d_in[12];
    const float* b_user = (const float*)d_in[13];
    const float* W_item = (const float*)d_in[14];
    const float* b_item = (const float*)d_in[15];
    float* out = (float*)d_out;

    int ne_ui = in_sizes[2];
    int ne_iu = in_sizes[4];
    int totE = ne_ui + ne_iu;

    void *p_aggf, *p_Wuh, *p_Wul, *p_Wih, *p_Wil, *p_cu, *p_ci, *p_cnt, *p_desc;
    cudaGetSymbolAddress(&p_aggf, g_aggf);
    cudaGetSymbolAddress(&p_Wuh, g_WuT_hi);
    cudaGetSymbolAddress(&p_Wul, g_WuT_lo);
    cudaGetSymbolAddress(&p_Wih, g_WiT_hi);
    cudaGetSymbolAddress(&p_Wil, g_WiT_lo);
    cudaGetSymbolAddress(&p_cu, g_cu);
    cudaGetSymbolAddress(&p_ci, g_ci);
    cudaGetSymbolAddress(&p_cnt, g_cnt);
    cudaGetSymbolAddress(&p_desc, (const void*)g_blkDesc);

    cudaFuncSetAttribute(node_gemm_mma, cudaFuncAttributeMaxDynamicSharedMemorySize, SM_TOTAL);

    static cudaStream_t s2 = nullptr;
    static cudaEvent_t evStart = nullptr, evComb = nullptr, evFill = nullptr, evDone = nullptr;
    if (s2 == nullptr) {
        cudaStreamCreateWithFlags(&s2, cudaStreamNonBlocking);
        cudaEventCreateWithFlags(&evStart, cudaEventDisableTiming);
        cudaEventCreateWithFlags(&evComb, cudaEventDisableTiming);
        cudaEventCreateWithFlags(&evFill, cudaEventDisableTiming);
        cudaEventCreateWithFlags(&evDone, cudaEventDisableTiming);
    }

    // fork s2 from the (capturing) default stream
    cudaEventRecord(evStart, 0);
    cudaStreamWaitEvent(s2, evStart, 0);

    // s2: weight combines (independent of CSR)
    combine_w<<<dim3(128, 4), 128, 0, s2>>>(Wl_iu, Wr_iu, Wl_ui, Wr_ui, W_user, W_item);
    combine_c<<<2, 128, 0, s2>>>(bl_iu, b_user, bl_ui, b_item, W_user, W_item);
    cudaEventRecord(evComb, s2);

    // main: CSR build (memset + hist + single-pass scan + fill)
    cudaMemsetAsync(p_cnt, 0, (size_t)NT * sizeof(int), 0);
    cudaMemsetAsync(p_desc, 0, 512 * sizeof(long long), 0);
    hist_all<<<(totE + 255) / 256, 256>>>(edst_iu, ne_iu, edst_ui, ne_ui);
    scan_chained<<<NBLK, 1024>>>(totE);
    fill_all<<<(totE + 255) / 256, 256>>>(esrc_iu, edst_iu, ne_iu, esrc_ui, edst_ui, ne_ui);
    cudaEventRecord(evFill, 0);

    // s2: full item chain — gather then GEMM (co-runs with user chain on main)
    cudaStreamWaitEvent(s2, evFill, 0);
    gather_part<<<(NII * 32 + 255) / 256, 256, 0, s2>>>(x_user, NUU, NT);
    node_gemm_mma<<<(NII + 127) / 128, 256, SM_TOTAL, s2>>>(
        (const __half*)p_aggf + (size_t)NUU * 128, x_item,
        (const __half*)p_Wih, (const __half*)p_Wil,
        (const float*)p_ci, out + (size_t)NUU * 128, NII);
    cudaEventRecord(evDone, s2);

    // main: user gather, then user GEMM (after combines)
    gather_part<<<(NUU * 32 + 255) / 256, 256>>>(x_item, 0, NUU);
    cudaStreamWaitEvent(0, evComb, 0);
    node_gemm_mma<<<(NUU + 127) / 128, 256, SM_TOTAL>>>(
        (const __half*)p_aggf, x_user,
        (const __half*)p_Wuh, (const __half*)p_Wul,
        (const float*)p_cu, out, NUU);

    // join item chain back into the captured stream
    cudaStreamWaitEvent(0, evDone, 0);
}